// round 11
// baseline (speedup 1.0000x reference)
#include <cuda_runtime.h>
#include <stdint.h>
#include <math.h>

#define BB   2
#define SS   2048
#define HH   16
#define DK   64
#define DM   1024
#define MTOT (BB*SS)          // 4096
#define BHT  (BB*HH)          // 32

__device__ float g_q[BB*HH*SS*DK];     // [b,h,s,d]
__device__ float g_k[BB*HH*SS*DK];
__device__ float g_v[BB*HH*SS*DK];
__device__ float g_ctx[BB*SS*DM];      // [b,s,dm]

// ---------------------------------------------------------------------------
// TF32 helpers
// ---------------------------------------------------------------------------
__device__ __forceinline__ float to_tf32(float x) {
    uint32_t u;
    asm("cvt.rna.tf32.f32 %0, %1;" : "=r"(u) : "f"(x));
    return __uint_as_float(u);
}

__device__ __forceinline__ void mma_tf32(float c[4],
                                         uint32_t a0, uint32_t a1, uint32_t a2, uint32_t a3,
                                         uint32_t b0, uint32_t b1) {
    asm volatile(
        "mma.sync.aligned.m16n8k8.row.col.f32.tf32.tf32.f32 "
        "{%0,%1,%2,%3}, {%4,%5,%6,%7}, {%8,%9}, {%0,%1,%2,%3};"
        : "+f"(c[0]), "+f"(c[1]), "+f"(c[2]), "+f"(c[3])
        : "r"(a0), "r"(a1), "r"(a2), "r"(a3), "r"(b0), "r"(b1));
}

__device__ __forceinline__ float ex2(float x) {
    float y;
    asm("ex2.approx.f32 %0, %1;" : "=f"(y) : "f"(x));
    return y;
}

#define FU(x) __float_as_uint(x)

// ---------------------------------------------------------------------------
// TF32 TC GEMM, double-buffered, k-permuted smem (col' = (k&3)*8 + (k>>2)),
// LDS.128 fragment feeds. C[m][n] = sum_k A[m][k] * W[n][k].
// MODE 0: z selects Wq/Wk/Wv, scatter to [b,h,s,d], RoPE fused for z<2.
// MODE 1: row-major out.
// ---------------------------------------------------------------------------
#define LDP 36
#define STG (256 * LDP)
#define GEMM_SMEM (2 * STG * 4)   // 73728 B

#define LOG2_10K_OVER32 (13.287712379549449f / 32.0f)

template<int MODE>
__global__ void __launch_bounds__(256, 2)
gemm_tf32_kernel(const float* __restrict__ A,
                 const float* __restrict__ W0, const float* __restrict__ W1,
                 const float* __restrict__ W2,
                 float* __restrict__ C0, float* __restrict__ C1, float* __restrict__ C2)
{
    extern __shared__ float smg[];

    const float* W;
    float* C;
    int z = 0;
    if (MODE == 0) {
        z = blockIdx.z;
        W = (z == 0) ? W0 : ((z == 1) ? W1 : W2);
        C = (z == 0) ? C0 : ((z == 1) ? C1 : C2);
    } else {
        W = W0; C = C0;
    }

    const int tid   = threadIdx.x;
    const int lane  = tid & 31;
    const int wid   = tid >> 5;
    const int warpM = wid >> 2;
    const int warpN = wid & 3;
    const int g     = lane >> 2;
    const int t     = lane & 3;

    const int m0 = blockIdx.y * 128;
    const int n0 = blockIdx.x * 128;

    const int ldRow = tid >> 3;         // 0..31
    const int ldCol = (tid & 7) * 4;    // 0..28
    const int j8    = tid & 7;          // k>>2 within tile

    const float* Abase = A + (size_t)(m0 + ldRow) * DM + ldCol;
    const float* Wbase = W + (size_t)(n0 + ldRow) * DM + ldCol;

    float acc[4][4][4];
#pragma unroll
    for (int mt = 0; mt < 4; mt++)
#pragma unroll
        for (int nt = 0; nt < 4; nt++)
#pragma unroll
            for (int r = 0; r < 4; r++) acc[mt][nt][r] = 0.f;

    // ---- prologue: fill stage 0 (permuted) ----
#pragma unroll
    for (int p = 0; p < 4; p++) {
        int r = ldRow + p * 32;
        float4 a4 = *(const float4*)(Abase + (size_t)p * 32 * DM);
        float* As = smg;
        As[r * LDP + j8     ] = to_tf32(a4.x);
        As[r * LDP + j8 + 8 ] = to_tf32(a4.y);
        As[r * LDP + j8 + 16] = to_tf32(a4.z);
        As[r * LDP + j8 + 24] = to_tf32(a4.w);
        float4 b4 = *(const float4*)(Wbase + (size_t)p * 32 * DM);
        float* Bs = smg + 128 * LDP;
        Bs[r * LDP + j8     ] = to_tf32(b4.x);
        Bs[r * LDP + j8 + 8 ] = to_tf32(b4.y);
        Bs[r * LDP + j8 + 16] = to_tf32(b4.z);
        Bs[r * LDP + j8 + 24] = to_tf32(b4.w);
    }

    for (int it = 0; it < 32; ++it) {
        __syncthreads();
        const float* Acur = smg + (it & 1) * STG;
        const float* Bcur = Acur + 128 * LDP;
        float* Anx = smg + ((it + 1) & 1) * STG;
        float* Bnx = Anx + 128 * LDP;
        const bool pf = (it + 1) < 32;
        const int kn = (it + 1) * 32;

        float4 sa[2], sb[2];
        if (pf) {
#pragma unroll
            for (int p = 0; p < 2; p++) {
                sa[p] = *(const float4*)(Abase + (size_t)p * 32 * DM + kn);
                sb[p] = *(const float4*)(Wbase + (size_t)p * 32 * DM + kn);
            }
        }

        // ---- half 0: ks 0,1 ----
        {
            float4 vb[4];
#pragma unroll
            for (int nt = 0; nt < 4; nt++)
                vb[nt] = *(const float4*)&Bcur[(warpN * 32 + nt * 8 + g) * LDP + t * 8];
#pragma unroll
            for (int mt = 0; mt < 4; mt++) {
                int row = warpM * 64 + mt * 16 + g;
                float4 va0 = *(const float4*)&Acur[(row    ) * LDP + t * 8];
                float4 va1 = *(const float4*)&Acur[(row + 8) * LDP + t * 8];
#pragma unroll
                for (int nt = 0; nt < 4; nt++) {
                    mma_tf32(acc[mt][nt], FU(va0.x), FU(va1.x), FU(va0.y), FU(va1.y),
                             FU(vb[nt].x), FU(vb[nt].y));
                    mma_tf32(acc[mt][nt], FU(va0.z), FU(va1.z), FU(va0.w), FU(va1.w),
                             FU(vb[nt].z), FU(vb[nt].w));
                }
            }
        }

        if (pf) {
#pragma unroll
            for (int p = 0; p < 2; p++) {
                int r = ldRow + p * 32;
                Anx[r * LDP + j8     ] = to_tf32(sa[p].x);
                Anx[r * LDP + j8 + 8 ] = to_tf32(sa[p].y);
                Anx[r * LDP + j8 + 16] = to_tf32(sa[p].z);
                Anx[r * LDP + j8 + 24] = to_tf32(sa[p].w);
                Bnx[r * LDP + j8     ] = to_tf32(sb[p].x);
                Bnx[r * LDP + j8 + 8 ] = to_tf32(sb[p].y);
                Bnx[r * LDP + j8 + 16] = to_tf32(sb[p].z);
                Bnx[r * LDP + j8 + 24] = to_tf32(sb[p].w);
            }
#pragma unroll
            for (int p = 0; p < 2; p++) {
                sa[p] = *(const float4*)(Abase + (size_t)(p + 2) * 32 * DM + kn);
                sb[p] = *(const float4*)(Wbase + (size_t)(p + 2) * 32 * DM + kn);
            }
        }

        // ---- half 1: ks 2,3 ----
        {
            float4 vb[4];
#pragma unroll
            for (int nt = 0; nt < 4; nt++)
                vb[nt] = *(const float4*)&Bcur[(warpN * 32 + nt * 8 + g) * LDP + t * 8 + 4];
#pragma unroll
            for (int mt = 0; mt < 4; mt++) {
                int row = warpM * 64 + mt * 16 + g;
                float4 va0 = *(const float4*)&Acur[(row    ) * LDP + t * 8 + 4];
                float4 va1 = *(const float4*)&Acur[(row + 8) * LDP + t * 8 + 4];
#pragma unroll
                for (int nt = 0; nt < 4; nt++) {
                    mma_tf32(acc[mt][nt], FU(va0.x), FU(va1.x), FU(va0.y), FU(va1.y),
                             FU(vb[nt].x), FU(vb[nt].y));
                    mma_tf32(acc[mt][nt], FU(va0.z), FU(va1.z), FU(va0.w), FU(va1.w),
                             FU(vb[nt].z), FU(vb[nt].w));
                }
            }
        }

        if (pf) {
#pragma unroll
            for (int p = 0; p < 2; p++) {
                int r = ldRow + (p + 2) * 32;
                Anx[r * LDP + j8     ] = to_tf32(sa[p].x);
                Anx[r * LDP + j8 + 8 ] = to_tf32(sa[p].y);
                Anx[r * LDP + j8 + 16] = to_tf32(sa[p].z);
                Anx[r * LDP + j8 + 24] = to_tf32(sa[p].w);
                Bnx[r * LDP + j8     ] = to_tf32(sb[p].x);
                Bnx[r * LDP + j8 + 8 ] = to_tf32(sb[p].y);
                Bnx[r * LDP + j8 + 16] = to_tf32(sb[p].z);
                Bnx[r * LDP + j8 + 24] = to_tf32(sb[p].w);
            }
        }
    }

    // ---- epilogue (fused RoPE for MODE 0, z<2) ----
#pragma unroll
    for (int mt = 0; mt < 4; mt++) {
#pragma unroll
        for (int nt = 0; nt < 4; nt++) {
            int r0  = m0 + warpM * 64 + mt * 16 + g;
            int col = n0 + warpN * 32 + nt * 8 + 2 * t;
            if (MODE == 0) {
                int h = col >> 6;
                int d = col & 63;
                float c0_ = acc[mt][nt][0], c1_ = acc[mt][nt][1];
                float c2_ = acc[mt][nt][2], c3_ = acc[mt][nt][3];
                if (z < 2) {
                    float invf = exp2f(-(float)(d >> 1) * LOG2_10K_OVER32);
#pragma unroll
                    for (int half = 0; half < 2; half++) {
                        int r = r0 + half * 8;
                        int s = r & 2047;
                        float sn, cs;
                        sincosf((float)s * invf, &sn, &cs);
                        float x1 = (half == 0) ? c0_ : c2_;
                        float x2 = (half == 0) ? c1_ : c3_;
                        float e = x1 * cs - x2 * sn;
                        float o = x1 * sn + x2 * cs;
                        if (half == 0) { c0_ = e; c1_ = o; }
                        else           { c2_ = e; c3_ = o; }
                    }
                }
#pragma unroll
                for (int half = 0; half < 2; half++) {
                    int r  = r0 + half * 8;
                    int b_ = r >> 11;
                    int s  = r & 2047;
                    float2* dst = (float2*)(C + ((size_t)((b_ * HH + h) * SS + s)) * DK + d);
                    *dst = (half == 0) ? make_float2(c0_, c1_) : make_float2(c2_, c3_);
                }
            } else {
#pragma unroll
                for (int half = 0; half < 2; half++) {
                    int r = r0 + half * 8;
                    float2* dst = (float2*)(C + (size_t)r * DM + col);
                    *dst = make_float2(acc[mt][nt][2 * half], acc[mt][nt][2 * half + 1]);
                }
            }
        }
    }
}

// ---------------------------------------------------------------------------
// TC flash attention (causal, tf32). Br=128, Bc=64, 256 threads.
// Q/K/P stored k-permuted per 32-block: col' = blk*32 + (k'&3)*8 + (k'>>2),
// stride FP=68 (≡4 mod 32) -> conflict-free LDS.128 fragment feeds.
// V stays [kv][n], stride VP=72 (scalar loads, already conflict-free).
// ---------------------------------------------------------------------------
#define FP 68
#define VP 72
#define SCALE2 0.1803368801111244f   // (1/8) * log2(e)

__global__ void __launch_bounds__(256, 2)
flash_tc_kernel(const float* __restrict__ Q, const float* __restrict__ K,
                const float* __restrict__ V, float* __restrict__ ctx)
{
    extern __shared__ float sm[];
    float* Qs = sm;                         // [128][FP] permuted
    float* Ps = Qs + 128 * FP;              // [128][FP] permuted
    float* Ks = Ps + 128 * FP;              // [64][FP]  permuted
    float* Vs = Ks + 64 * FP;               // [64][VP]

    const int tid  = threadIdx.x;
    const int lane = tid & 31;
    const int w    = tid >> 5;
    const int g    = lane >> 2;
    const int t    = lane & 3;

    const int qb  = gridDim.x - 1 - blockIdx.x;
    const int bh  = blockIdx.y;
    const int qr0 = qb * 128;

    const float* Qb = Q + (size_t)bh * SS * DK;
    const float* Kb = K + (size_t)bh * SS * DK;
    const float* Vb = V + (size_t)bh * SS * DK;

    // Load Q tile (pre-scaled, tf32, permuted)
#pragma unroll
    for (int u = 0; u < 8; u++) {
        int idx = tid + u * 256;
        int r   = idx >> 4;
        int c4  = (idx & 15) << 2;
        int cb  = ((idx >> 3) & 1) * 32 + (idx & 7);
        float4 q4 = *(const float4*)(Qb + (size_t)(qr0 + r) * DK + c4);
        Qs[r * FP + cb     ] = to_tf32(q4.x * SCALE2);
        Qs[r * FP + cb + 8 ] = to_tf32(q4.y * SCALE2);
        Qs[r * FP + cb + 16] = to_tf32(q4.z * SCALE2);
        Qs[r * FP + cb + 24] = to_tf32(q4.w * SCALE2);
    }

    float of[8][4];
#pragma unroll
    for (int nt = 0; nt < 8; nt++)
#pragma unroll
        for (int r = 0; r < 4; r++) of[nt][r] = 0.f;
    float m0 = -1e30f, m1 = -1e30f, l0 = 0.f, l1 = 0.f;

    const int row0 = w * 16 + g;
    const int ntiles = 2 * qb + 2;

    for (int tt = 0; tt < ntiles; ++tt) {
        const int kc0 = tt * 64;
        __syncthreads();
        // fill K (permuted) and V (plain) tiles
#pragma unroll
        for (int u = 0; u < 4; u++) {
            int idx = tid + u * 256;
            int r   = idx >> 4;
            int c4  = (idx & 15) << 2;
            int cb  = ((idx >> 3) & 1) * 32 + (idx & 7);
            float4 k4 = *(const float4*)(Kb + (size_t)(kc0 + r) * DK + c4);
            Ks[r * FP + cb     ] = to_tf32(k4.x);
            Ks[r * FP + cb + 8 ] = to_tf32(k4.y);
            Ks[r * FP + cb + 16] = to_tf32(k4.z);
            Ks[r * FP + cb + 24] = to_tf32(k4.w);
            float4 v4 = *(const float4*)(Vb + (size_t)(kc0 + r) * DK + c4);
            *(float4*)&Vs[r * VP + c4] = make_float4(to_tf32(v4.x), to_tf32(v4.y),
                                                     to_tf32(v4.z), to_tf32(v4.w));
        }
        __syncthreads();

        // ---- S = Q' K^T ----
        float sc[8][4];
#pragma unroll
        for (int nt = 0; nt < 8; nt++)
#pragma unroll
            for (int r = 0; r < 4; r++) sc[nt][r] = 0.f;

#pragma unroll
        for (int blk = 0; blk < 2; blk++) {
#pragma unroll
            for (int h = 0; h < 2; h++) {
                const int cb = blk * 32 + t * 8 + h * 4;
                float4 va0 = *(const float4*)&Qs[(w * 16 + g    ) * FP + cb];
                float4 va1 = *(const float4*)&Qs[(w * 16 + g + 8) * FP + cb];
#pragma unroll
                for (int nt = 0; nt < 8; nt++) {
                    float4 vb = *(const float4*)&Ks[(nt * 8 + g) * FP + cb];
                    mma_tf32(sc[nt], FU(va0.x), FU(va1.x), FU(va0.y), FU(va1.y),
                             FU(vb.x), FU(vb.y));
                    mma_tf32(sc[nt], FU(va0.z), FU(va1.z), FU(va0.w), FU(va1.w),
                             FU(vb.z), FU(vb.w));
                }
            }
        }

        if (tt >= 2 * qb) {
            const int rg0 = qr0 + row0;
            const int rg1 = rg0 + 8;
#pragma unroll
            for (int nt = 0; nt < 8; nt++) {
                int jg = kc0 + nt * 8 + 2 * t;
                if (jg     > rg0) sc[nt][0] = -1e30f;
                if (jg + 1 > rg0) sc[nt][1] = -1e30f;
                if (jg     > rg1) sc[nt][2] = -1e30f;
                if (jg + 1 > rg1) sc[nt][3] = -1e30f;
            }
        }

        float mx0 = -1e30f, mx1 = -1e30f;
#pragma unroll
        for (int nt = 0; nt < 8; nt++) {
            mx0 = fmaxf(mx0, fmaxf(sc[nt][0], sc[nt][1]));
            mx1 = fmaxf(mx1, fmaxf(sc[nt][2], sc[nt][3]));
        }
        mx0 = fmaxf(mx0, __shfl_xor_sync(0xffffffffu, mx0, 1));
        mx0 = fmaxf(mx0, __shfl_xor_sync(0xffffffffu, mx0, 2));
        mx1 = fmaxf(mx1, __shfl_xor_sync(0xffffffffu, mx1, 1));
        mx1 = fmaxf(mx1, __shfl_xor_sync(0xffffffffu, mx1, 2));

        float m0n = fmaxf(m0, mx0);
        float m1n = fmaxf(m1, mx1);
        float corr0 = ex2(m0 - m0n);
        float corr1 = ex2(m1 - m1n);
        m0 = m0n; m1 = m1n;

        float s0 = 0.f, s1 = 0.f;
#pragma unroll
        for (int nt = 0; nt < 8; nt++) {
            float p0 = ex2(sc[nt][0] - m0n);
            float p1 = ex2(sc[nt][1] - m0n);
            float p2 = ex2(sc[nt][2] - m1n);
            float p3 = ex2(sc[nt][3] - m1n);
            s0 += p0 + p1;
            s1 += p2 + p3;
            // permuted store: k = nt*8 + 2t (and +1 -> col+8)
            int cbp = ((nt >> 2) * 32) + ((t & 1) * 16) + 2 * (nt & 3) + (t >> 1);
            Ps[(w * 16 + g    ) * FP + cbp    ] = to_tf32(p0);
            Ps[(w * 16 + g    ) * FP + cbp + 8] = to_tf32(p1);
            Ps[(w * 16 + g + 8) * FP + cbp    ] = to_tf32(p2);
            Ps[(w * 16 + g + 8) * FP + cbp + 8] = to_tf32(p3);
        }
        s0 += __shfl_xor_sync(0xffffffffu, s0, 1);
        s0 += __shfl_xor_sync(0xffffffffu, s0, 2);
        s1 += __shfl_xor_sync(0xffffffffu, s1, 1);
        s1 += __shfl_xor_sync(0xffffffffu, s1, 2);
        l0 = l0 * corr0 + s0;
        l1 = l1 * corr1 + s1;

#pragma unroll
        for (int nt = 0; nt < 8; nt++) {
            of[nt][0] *= corr0; of[nt][1] *= corr0;
            of[nt][2] *= corr1; of[nt][3] *= corr1;
        }
        __syncwarp();

        // ---- O += P V ----
#pragma unroll
        for (int blk = 0; blk < 2; blk++) {
#pragma unroll
            for (int h = 0; h < 2; h++) {
                const int cb = blk * 32 + t * 8 + h * 4;
                float4 va0 = *(const float4*)&Ps[(w * 16 + g    ) * FP + cb];
                float4 va1 = *(const float4*)&Ps[(w * 16 + g + 8) * FP + cb];
#pragma unroll
                for (int s = 0; s < 2; s++) {
                    const int kb = blk * 32 + h * 16 + s * 8;
                    uint32_t a0 = (s == 0) ? FU(va0.x) : FU(va0.z);
                    uint32_t a1 = (s == 0) ? FU(va1.x) : FU(va1.z);
                    uint32_t a2 = (s == 0) ? FU(va0.y) : FU(va0.w);
                    uint32_t a3 = (s == 0) ? FU(va1.y) : FU(va1.w);
#pragma unroll
                    for (int nt = 0; nt < 8; nt++) {
                        uint32_t b0 = FU(Vs[(kb + t    ) * VP + nt * 8 + g]);
                        uint32_t b1 = FU(Vs[(kb + t + 4) * VP + nt * 8 + g]);
                        mma_tf32(of[nt], a0, a1, a2, a3, b0, b1);
                    }
                }
            }
        }
    }

    const int b = bh >> 4;
    const int h = bh & 15;
    float inv0 = 1.0f / l0;
    float inv1 = 1.0f / l1;
    int srow0 = qr0 + row0;
    float* dst0 = ctx + ((size_t)(b * SS + srow0)) * DM + h * 64;
    float* dst1 = ctx + ((size_t)(b * SS + srow0 + 8)) * DM + h * 64;
#pragma unroll
    for (int nt = 0; nt < 8; nt++) {
        int cb = nt * 8 + 2 * t;
        *(float2*)&dst0[cb] = make_float2(of[nt][0] * inv0, of[nt][1] * inv0);
        *(float2*)&dst1[cb] = make_float2(of[nt][2] * inv1, of[nt][3] * inv1);
    }
}

// ---------------------------------------------------------------------------
extern "C" void kernel_launch(void* const* d_in, const int* in_sizes, int n_in,
                              void* d_out, int out_size)
{
    const float* x  = (const float*)d_in[0];
    const float* Wq = (const float*)d_in[1];
    const float* Wk = (const float*)d_in[2];
    const float* Wv = (const float*)d_in[3];
    const float* Wo = (const float*)d_in[4];
    float* out = (float*)d_out;

    float *qp, *kp, *vp, *cp;
    cudaGetSymbolAddress((void**)&qp, g_q);
    cudaGetSymbolAddress((void**)&kp, g_k);
    cudaGetSymbolAddress((void**)&vp, g_v);
    cudaGetSymbolAddress((void**)&cp, g_ctx);

    cudaFuncSetAttribute(gemm_tf32_kernel<0>,
                         cudaFuncAttributeMaxDynamicSharedMemorySize, GEMM_SMEM);
    cudaFuncSetAttribute(gemm_tf32_kernel<1>,
                         cudaFuncAttributeMaxDynamicSharedMemorySize, GEMM_SMEM);

    // 1. QKV projection (fused 3-way, tf32 TC, pipelined, RoPE fused for Q/K)
    gemm_tf32_kernel<0><<<dim3(DM / 128, MTOT / 128, 3), 256, GEMM_SMEM>>>(
        x, Wq, Wk, Wv, qp, kp, vp);

    // 2. Causal flash attention (tf32 tensor cores)
    {
        const int smem_bytes = (128 * FP + 128 * FP + 64 * FP + 64 * VP) * 4; // 105472
        cudaFuncSetAttribute(flash_tc_kernel,
                             cudaFuncAttributeMaxDynamicSharedMemorySize,
                             smem_bytes);
        flash_tc_kernel<<<dim3(SS / 128, BHT), 256, smem_bytes>>>(qp, kp, vp, cp);
    }

    // 3. Output projection (tf32 tensor cores, pipelined)
    gemm_tf32_kernel<1><<<dim3(DM / 128, MTOT / 128, 1), 256, GEMM_SMEM>>>(
        cp, Wo, Wo, Wo, out, out, out);
}

// round 13
// speedup vs baseline: 1.2109x; 1.2109x over previous
#include <cuda_runtime.h>
#include <stdint.h>
#include <math.h>

#define BB   2
#define SS   2048
#define HH   16
#define DK   64
#define DM   1024
#define MTOT (BB*SS)          // 4096
#define BHT  (BB*HH)          // 32

__device__ float g_q[BB*HH*SS*DK];     // [b,h,s,d]
__device__ float g_k[BB*HH*SS*DK];
__device__ float g_v[BB*HH*SS*DK];
__device__ float g_ctx[BB*SS*DM];      // [b,s,dm]
__device__ float2 g_rope[SS*32];       // [s][j] = (cos, sin)

// ---------------------------------------------------------------------------
// TF32 helpers
// ---------------------------------------------------------------------------
__device__ __forceinline__ float to_tf32(float x) {
    uint32_t u;
    asm("cvt.rna.tf32.f32 %0, %1;" : "=r"(u) : "f"(x));
    return __uint_as_float(u);
}

__device__ __forceinline__ void mma_tf32(float c[4],
                                         uint32_t a0, uint32_t a1, uint32_t a2, uint32_t a3,
                                         uint32_t b0, uint32_t b1) {
    asm volatile(
        "mma.sync.aligned.m16n8k8.row.col.f32.tf32.tf32.f32 "
        "{%0,%1,%2,%3}, {%4,%5,%6,%7}, {%8,%9}, {%0,%1,%2,%3};"
        : "+f"(c[0]), "+f"(c[1]), "+f"(c[2]), "+f"(c[3])
        : "r"(a0), "r"(a1), "r"(a2), "r"(a3), "r"(b0), "r"(b1));
}

__device__ __forceinline__ float ex2(float x) {
    float y;
    asm("ex2.approx.f32 %0, %1;" : "=f"(y) : "f"(x));
    return y;
}

#define LOG2_10K_OVER32 (13.287712379549449f / 32.0f)

// ---------------------------------------------------------------------------
// RoPE cos/sin table: g_rope[s*32 + j] = (cos(s*invf_j), sin(s*invf_j))
// ---------------------------------------------------------------------------
__global__ void rope_table_kernel()
{
    int idx = blockIdx.x * blockDim.x + threadIdx.x;
    if (idx >= SS * 32) return;
    int j = idx & 31;
    int s = idx >> 5;
    float invf = exp2f(-(float)j * LOG2_10K_OVER32);
    float sn, cs;
    sincosf((float)s * invf, &sn, &cs);
    g_rope[idx] = make_float2(cs, sn);
}

// ---------------------------------------------------------------------------
// TF32 tensor-core GEMM, double-buffered + software pipelined (R10 layout).
// C[m][n] = sum_k A[m][k] * W[n][k]
// MODE 0: z selects Wq/Wk/Wv; epilogue scatters into [b,h,s,d]; z<2 RoPE (table)
// MODE 1: plain row-major output
// ---------------------------------------------------------------------------
#define LDP 36
#define STG (256 * LDP)
#define GEMM_SMEM (2 * STG * 4)   // 73728 B

template<int MODE>
__global__ void __launch_bounds__(256, 2)
gemm_tf32_kernel(const float* __restrict__ A,
                 const float* __restrict__ W0, const float* __restrict__ W1,
                 const float* __restrict__ W2,
                 float* __restrict__ C0, float* __restrict__ C1, float* __restrict__ C2)
{
    extern __shared__ float smg[];

    const float* W;
    float* C;
    int z = 0;
    if (MODE == 0) {
        z = blockIdx.z;
        W = (z == 0) ? W0 : ((z == 1) ? W1 : W2);
        C = (z == 0) ? C0 : ((z == 1) ? C1 : C2);
    } else {
        W = W0; C = C0;
    }

    const int tid   = threadIdx.x;
    const int lane  = tid & 31;
    const int wid   = tid >> 5;
    const int warpM = wid >> 2;
    const int warpN = wid & 3;
    const int g     = lane >> 2;
    const int t     = lane & 3;

    const int m0 = blockIdx.y * 128;
    const int n0 = blockIdx.x * 128;

    const int ldRow = tid >> 3;         // 0..31
    const int ldCol = (tid & 7) * 4;    // 0,4,...,28

    const float* Abase = A + (size_t)(m0 + ldRow) * DM + ldCol;
    const float* Wbase = W + (size_t)(n0 + ldRow) * DM + ldCol;

    float acc[4][4][4];
#pragma unroll
    for (int mt = 0; mt < 4; mt++)
#pragma unroll
        for (int nt = 0; nt < 4; nt++)
#pragma unroll
            for (int r = 0; r < 4; r++) acc[mt][nt][r] = 0.f;

    // ---- prologue: fill stage 0 with tile 0 ----
#pragma unroll
    for (int p = 0; p < 4; p++) {
        int r = ldRow + p * 32;
        float4 a4 = *(const float4*)(Abase + (size_t)p * 32 * DM);
        float* As = smg;
        As[r * LDP + ldCol + 0] = to_tf32(a4.x);
        As[r * LDP + ldCol + 1] = to_tf32(a4.y);
        As[r * LDP + ldCol + 2] = to_tf32(a4.z);
        As[r * LDP + ldCol + 3] = to_tf32(a4.w);
        float4 b4 = *(const float4*)(Wbase + (size_t)p * 32 * DM);
        float* Bs = smg + 128 * LDP;
        Bs[r * LDP + ldCol + 0] = to_tf32(b4.x);
        Bs[r * LDP + ldCol + 1] = to_tf32(b4.y);
        Bs[r * LDP + ldCol + 2] = to_tf32(b4.z);
        Bs[r * LDP + ldCol + 3] = to_tf32(b4.w);
    }

    for (int it = 0; it < 32; ++it) {
        __syncthreads();
        const float* Acur = smg + (it & 1) * STG;
        const float* Bcur = Acur + 128 * LDP;
        float* Anx = smg + ((it + 1) & 1) * STG;
        float* Bnx = Anx + 128 * LDP;
        const bool pf = (it + 1) < 32;
        const int kn = (it + 1) * 32;

        float4 sa[2], sb[2];
        if (pf) {
#pragma unroll
            for (int p = 0; p < 2; p++) {
                sa[p] = *(const float4*)(Abase + (size_t)p * 32 * DM + kn);
                sb[p] = *(const float4*)(Wbase + (size_t)p * 32 * DM + kn);
            }
        }

        // ---- compute ks = 0,1 ----
#pragma unroll
        for (int ks = 0; ks < 2; ks++) {
            const int kk = ks * 8;
            uint32_t afr[4][4], bfr[4][2];
#pragma unroll
            for (int mt = 0; mt < 4; mt++) {
                int row = warpM * 64 + mt * 16 + g;
                afr[mt][0] = __float_as_uint(Acur[(row    ) * LDP + kk + t    ]);
                afr[mt][1] = __float_as_uint(Acur[(row + 8) * LDP + kk + t    ]);
                afr[mt][2] = __float_as_uint(Acur[(row    ) * LDP + kk + t + 4]);
                afr[mt][3] = __float_as_uint(Acur[(row + 8) * LDP + kk + t + 4]);
            }
#pragma unroll
            for (int nt = 0; nt < 4; nt++) {
                int col = warpN * 32 + nt * 8 + g;
                bfr[nt][0] = __float_as_uint(Bcur[col * LDP + kk + t    ]);
                bfr[nt][1] = __float_as_uint(Bcur[col * LDP + kk + t + 4]);
            }
#pragma unroll
            for (int mt = 0; mt < 4; mt++)
#pragma unroll
                for (int nt = 0; nt < 4; nt++)
                    mma_tf32(acc[mt][nt],
                             afr[mt][0], afr[mt][1], afr[mt][2], afr[mt][3],
                             bfr[nt][0], bfr[nt][1]);
        }

        if (pf) {
#pragma unroll
            for (int p = 0; p < 2; p++) {
                int r = ldRow + p * 32;
                Anx[r * LDP + ldCol + 0] = to_tf32(sa[p].x);
                Anx[r * LDP + ldCol + 1] = to_tf32(sa[p].y);
                Anx[r * LDP + ldCol + 2] = to_tf32(sa[p].z);
                Anx[r * LDP + ldCol + 3] = to_tf32(sa[p].w);
                Bnx[r * LDP + ldCol + 0] = to_tf32(sb[p].x);
                Bnx[r * LDP + ldCol + 1] = to_tf32(sb[p].y);
                Bnx[r * LDP + ldCol + 2] = to_tf32(sb[p].z);
                Bnx[r * LDP + ldCol + 3] = to_tf32(sb[p].w);
            }
#pragma unroll
            for (int p = 0; p < 2; p++) {
                sa[p] = *(const float4*)(Abase + (size_t)(p + 2) * 32 * DM + kn);
                sb[p] = *(const float4*)(Wbase + (size_t)(p + 2) * 32 * DM + kn);
            }
        }

        // ---- compute ks = 2,3 ----
#pragma unroll
        for (int ks = 2; ks < 4; ks++) {
            const int kk = ks * 8;
            uint32_t afr[4][4], bfr[4][2];
#pragma unroll
            for (int mt = 0; mt < 4; mt++) {
                int row = warpM * 64 + mt * 16 + g;
                afr[mt][0] = __float_as_uint(Acur[(row    ) * LDP + kk + t    ]);
                afr[mt][1] = __float_as_uint(Acur[(row + 8) * LDP + kk + t    ]);
                afr[mt][2] = __float_as_uint(Acur[(row    ) * LDP + kk + t + 4]);
                afr[mt][3] = __float_as_uint(Acur[(row + 8) * LDP + kk + t + 4]);
            }
#pragma unroll
            for (int nt = 0; nt < 4; nt++) {
                int col = warpN * 32 + nt * 8 + g;
                bfr[nt][0] = __float_as_uint(Bcur[col * LDP + kk + t    ]);
                bfr[nt][1] = __float_as_uint(Bcur[col * LDP + kk + t + 4]);
            }
#pragma unroll
            for (int mt = 0; mt < 4; mt++)
#pragma unroll
                for (int nt = 0; nt < 4; nt++)
                    mma_tf32(acc[mt][nt],
                             afr[mt][0], afr[mt][1], afr[mt][2], afr[mt][3],
                             bfr[nt][0], bfr[nt][1]);
        }

        if (pf) {
#pragma unroll
            for (int p = 0; p < 2; p++) {
                int r = ldRow + (p + 2) * 32;
                Anx[r * LDP + ldCol + 0] = to_tf32(sa[p].x);
                Anx[r * LDP + ldCol + 1] = to_tf32(sa[p].y);
                Anx[r * LDP + ldCol + 2] = to_tf32(sa[p].z);
                Anx[r * LDP + ldCol + 3] = to_tf32(sa[p].w);
                Bnx[r * LDP + ldCol + 0] = to_tf32(sb[p].x);
                Bnx[r * LDP + ldCol + 1] = to_tf32(sb[p].y);
                Bnx[r * LDP + ldCol + 2] = to_tf32(sb[p].z);
                Bnx[r * LDP + ldCol + 3] = to_tf32(sb[p].w);
            }
        }
    }

    // ---- epilogue (fused RoPE via table for MODE 0, z<2) ----
#pragma unroll
    for (int mt = 0; mt < 4; mt++) {
#pragma unroll
        for (int nt = 0; nt < 4; nt++) {
            int r0  = m0 + warpM * 64 + mt * 16 + g;
            int col = n0 + warpN * 32 + nt * 8 + 2 * t;
            if (MODE == 0) {
                int h = col >> 6;
                int d = col & 63;
                float c0_ = acc[mt][nt][0], c1_ = acc[mt][nt][1];
                float c2_ = acc[mt][nt][2], c3_ = acc[mt][nt][3];
                if (z < 2) {
                    int j = d >> 1;
#pragma unroll
                    for (int half = 0; half < 2; half++) {
                        int r = r0 + half * 8;
                        int s = r & 2047;
                        float2 cspair = g_rope[s * 32 + j];
                        float x1 = (half == 0) ? c0_ : c2_;
                        float x2 = (half == 0) ? c1_ : c3_;
                        float e = x1 * cspair.x - x2 * cspair.y;
                        float o = x1 * cspair.y + x2 * cspair.x;
                        if (half == 0) { c0_ = e; c1_ = o; }
                        else           { c2_ = e; c3_ = o; }
                    }
                }
#pragma unroll
                for (int half = 0; half < 2; half++) {
                    int r  = r0 + half * 8;
                    int b_ = r >> 11;
                    int s  = r & 2047;
                    float2* dst = (float2*)(C + ((size_t)((b_ * HH + h) * SS + s)) * DK + d);
                    *dst = (half == 0) ? make_float2(c0_, c1_) : make_float2(c2_, c3_);
                }
            } else {
#pragma unroll
                for (int half = 0; half < 2; half++) {
                    int r = r0 + half * 8;
                    float2* dst = (float2*)(C + (size_t)r * DM + col);
                    *dst = make_float2(acc[mt][nt][2 * half], acc[mt][nt][2 * half + 1]);
                }
            }
        }
    }
}

// ---------------------------------------------------------------------------
// Tensor-core flash attention (causal, tf32). Br=128, Bc=64, 256 threads.
// (Exact R10 version — best measured.)
// ---------------------------------------------------------------------------
#define FP 68
#define VP 72
#define SCALE2 0.1803368801111244f   // (1/8) * log2(e)

__global__ void __launch_bounds__(256, 2)
flash_tc_kernel(const float* __restrict__ Q, const float* __restrict__ K,
                const float* __restrict__ V, float* __restrict__ ctx)
{
    extern __shared__ float sm[];
    float* Qs = sm;                         // [128][FP]
    float* Ps = Qs + 128 * FP;              // [128][FP]
    float* Ks = Ps + 128 * FP;              // [64][FP]
    float* Vs = Ks + 64 * FP;               // [64][VP]

    const int tid  = threadIdx.x;
    const int lane = tid & 31;
    const int w    = tid >> 5;
    const int g    = lane >> 2;
    const int t    = lane & 3;

    const int qb  = gridDim.x - 1 - blockIdx.x;
    const int bh  = blockIdx.y;
    const int qr0 = qb * 128;

    const float* Qb = Q + (size_t)bh * SS * DK;
    const float* Kb = K + (size_t)bh * SS * DK;
    const float* Vb = V + (size_t)bh * SS * DK;

#pragma unroll
    for (int u = 0; u < 8; u++) {
        int idx = tid + u * 256;
        int r   = idx >> 4;
        int c4  = (idx & 15) << 2;
        float4 q4 = *(const float4*)(Qb + (size_t)(qr0 + r) * DK + c4);
        float4 s4 = make_float4(to_tf32(q4.x * SCALE2), to_tf32(q4.y * SCALE2),
                                to_tf32(q4.z * SCALE2), to_tf32(q4.w * SCALE2));
        *(float4*)&Qs[r * FP + c4] = s4;
    }

    float of[8][4];
#pragma unroll
    for (int nt = 0; nt < 8; nt++)
#pragma unroll
        for (int r = 0; r < 4; r++) of[nt][r] = 0.f;
    float m0 = -1e30f, m1 = -1e30f, l0 = 0.f, l1 = 0.f;

    const int row0 = w * 16 + g;
    const int ntiles = 2 * qb + 2;

    for (int tt = 0; tt < ntiles; ++tt) {
        const int kc0 = tt * 64;
        __syncthreads();
#pragma unroll
        for (int u = 0; u < 4; u++) {
            int idx = tid + u * 256;
            int r   = idx >> 4;
            int c4  = (idx & 15) << 2;
            float4 k4 = *(const float4*)(Kb + (size_t)(kc0 + r) * DK + c4);
            *(float4*)&Ks[r * FP + c4] = make_float4(to_tf32(k4.x), to_tf32(k4.y),
                                                     to_tf32(k4.z), to_tf32(k4.w));
            float4 v4 = *(const float4*)(Vb + (size_t)(kc0 + r) * DK + c4);
            *(float4*)&Vs[r * VP + c4] = make_float4(to_tf32(v4.x), to_tf32(v4.y),
                                                     to_tf32(v4.z), to_tf32(v4.w));
        }
        __syncthreads();

        float sc[8][4];
#pragma unroll
        for (int nt = 0; nt < 8; nt++)
#pragma unroll
            for (int r = 0; r < 4; r++) sc[nt][r] = 0.f;

#pragma unroll
        for (int kk = 0; kk < 8; kk++) {
            const int kb = kk * 8;
            uint32_t a0 = __float_as_uint(Qs[(w * 16 + g    ) * FP + kb + t    ]);
            uint32_t a1 = __float_as_uint(Qs[(w * 16 + g + 8) * FP + kb + t    ]);
            uint32_t a2 = __float_as_uint(Qs[(w * 16 + g    ) * FP + kb + t + 4]);
            uint32_t a3 = __float_as_uint(Qs[(w * 16 + g + 8) * FP + kb + t + 4]);
#pragma unroll
            for (int nt = 0; nt < 8; nt++) {
                uint32_t b0 = __float_as_uint(Ks[(nt * 8 + g) * FP + kb + t    ]);
                uint32_t b1 = __float_as_uint(Ks[(nt * 8 + g) * FP + kb + t + 4]);
                mma_tf32(sc[nt], a0, a1, a2, a3, b0, b1);
            }
        }

        if (tt >= 2 * qb) {
            const int rg0 = qr0 + row0;
            const int rg1 = rg0 + 8;
#pragma unroll
            for (int nt = 0; nt < 8; nt++) {
                int jg = kc0 + nt * 8 + 2 * t;
                if (jg     > rg0) sc[nt][0] = -1e30f;
                if (jg + 1 > rg0) sc[nt][1] = -1e30f;
                if (jg     > rg1) sc[nt][2] = -1e30f;
                if (jg + 1 > rg1) sc[nt][3] = -1e30f;
            }
        }

        float mx0 = -1e30f, mx1 = -1e30f;
#pragma unroll
        for (int nt = 0; nt < 8; nt++) {
            mx0 = fmaxf(mx0, fmaxf(sc[nt][0], sc[nt][1]));
            mx1 = fmaxf(mx1, fmaxf(sc[nt][2], sc[nt][3]));
        }
        mx0 = fmaxf(mx0, __shfl_xor_sync(0xffffffffu, mx0, 1));
        mx0 = fmaxf(mx0, __shfl_xor_sync(0xffffffffu, mx0, 2));
        mx1 = fmaxf(mx1, __shfl_xor_sync(0xffffffffu, mx1, 1));
        mx1 = fmaxf(mx1, __shfl_xor_sync(0xffffffffu, mx1, 2));

        float m0n = fmaxf(m0, mx0);
        float m1n = fmaxf(m1, mx1);
        float corr0 = ex2(m0 - m0n);
        float corr1 = ex2(m1 - m1n);
        m0 = m0n; m1 = m1n;

        float s0 = 0.f, s1 = 0.f;
#pragma unroll
        for (int nt = 0; nt < 8; nt++) {
            float p0 = ex2(sc[nt][0] - m0n);
            float p1 = ex2(sc[nt][1] - m0n);
            float p2 = ex2(sc[nt][2] - m1n);
            float p3 = ex2(sc[nt][3] - m1n);
            s0 += p0 + p1;
            s1 += p2 + p3;
            int cb = nt * 8 + 2 * t;
            *(float2*)&Ps[(w * 16 + g    ) * FP + cb] = make_float2(to_tf32(p0), to_tf32(p1));
            *(float2*)&Ps[(w * 16 + g + 8) * FP + cb] = make_float2(to_tf32(p2), to_tf32(p3));
        }
        s0 += __shfl_xor_sync(0xffffffffu, s0, 1);
        s0 += __shfl_xor_sync(0xffffffffu, s0, 2);
        s1 += __shfl_xor_sync(0xffffffffu, s1, 1);
        s1 += __shfl_xor_sync(0xffffffffu, s1, 2);
        l0 = l0 * corr0 + s0;
        l1 = l1 * corr1 + s1;

#pragma unroll
        for (int nt = 0; nt < 8; nt++) {
            of[nt][0] *= corr0; of[nt][1] *= corr0;
            of[nt][2] *= corr1; of[nt][3] *= corr1;
        }
        __syncwarp();

#pragma unroll
        for (int kk = 0; kk < 8; kk++) {
            const int kb = kk * 8;
            uint32_t a0 = __float_as_uint(Ps[(w * 16 + g    ) * FP + kb + t    ]);
            uint32_t a1 = __float_as_uint(Ps[(w * 16 + g + 8) * FP + kb + t    ]);
            uint32_t a2 = __float_as_uint(Ps[(w * 16 + g    ) * FP + kb + t + 4]);
            uint32_t a3 = __float_as_uint(Ps[(w * 16 + g + 8) * FP + kb + t + 4]);
#pragma unroll
            for (int nt = 0; nt < 8; nt++) {
                uint32_t b0 = __float_as_uint(Vs[(kb + t    ) * VP + nt * 8 + g]);
                uint32_t b1 = __float_as_uint(Vs[(kb + t + 4) * VP + nt * 8 + g]);
                mma_tf32(of[nt], a0, a1, a2, a3, b0, b1);
            }
        }
    }

    const int b = bh >> 4;
    const int h = bh & 15;
    float inv0 = 1.0f / l0;
    float inv1 = 1.0f / l1;
    int srow0 = qr0 + row0;
    float* dst0 = ctx + ((size_t)(b * SS + srow0)) * DM + h * 64;
    float* dst1 = ctx + ((size_t)(b * SS + srow0 + 8)) * DM + h * 64;
#pragma unroll
    for (int nt = 0; nt < 8; nt++) {
        int cb = nt * 8 + 2 * t;
        *(float2*)&dst0[cb] = make_float2(of[nt][0] * inv0, of[nt][1] * inv0);
        *(float2*)&dst1[cb] = make_float2(of[nt][2] * inv1, of[nt][3] * inv1);
    }
}

// ---------------------------------------------------------------------------
extern "C" void kernel_launch(void* const* d_in, const int* in_sizes, int n_in,
                              void* d_out, int out_size)
{
    const float* x  = (const float*)d_in[0];
    const float* Wq = (const float*)d_in[1];
    const float* Wk = (const float*)d_in[2];
    const float* Wv = (const float*)d_in[3];
    const float* Wo = (const float*)d_in[4];
    float* out = (float*)d_out;

    float *qp, *kp, *vp, *cp;
    cudaGetSymbolAddress((void**)&qp, g_q);
    cudaGetSymbolAddress((void**)&kp, g_k);
    cudaGetSymbolAddress((void**)&vp, g_v);
    cudaGetSymbolAddress((void**)&cp, g_ctx);

    cudaFuncSetAttribute(gemm_tf32_kernel<0>,
                         cudaFuncAttributeMaxDynamicSharedMemorySize, GEMM_SMEM);
    cudaFuncSetAttribute(gemm_tf32_kernel<1>,
                         cudaFuncAttributeMaxDynamicSharedMemorySize, GEMM_SMEM);

    // 0. RoPE cos/sin table (overlaps nothing; tiny)
    rope_table_kernel<<<(SS * 32 + 255) / 256, 256>>>();

    // 1. QKV projection (fused 3-way, tf32 TC, pipelined, RoPE fused via table)
    gemm_tf32_kernel<0><<<dim3(DM / 128, MTOT / 128, 3), 256, GEMM_SMEM>>>(
        x, Wq, Wk, Wv, qp, kp, vp);

    // 2. Causal flash attention (tf32 tensor cores)
    {
        const int smem_bytes = (128 * FP + 128 * FP + 64 * FP + 64 * VP) * 4; // 105472
        cudaFuncSetAttribute(flash_tc_kernel,
                             cudaFuncAttributeMaxDynamicSharedMemorySize,
                             smem_bytes);
        flash_tc_kernel<<<dim3(SS / 128, BHT), 256, smem_bytes>>>(qp, kp, vp, cp);
    }

    // 3. Output projection (tf32 tensor cores, pipelined)
    gemm_tf32_kernel<1><<<dim3(DM / 128, MTOT / 128, 1), 256, GEMM_SMEM>>>(
        cp, Wo, Wo, Wo, out, out, out);
}